// round 2
// baseline (speedup 1.0000x reference)
#include <cuda_runtime.h>
#include <cuda_bf16.h>
#include <math.h>

// ----------------------------------------------------------------------------
// TransformerEncoder baseline (round 1): pure fp32, fused epilogues,
// flash-style attention with off-by-one online softmax.
// B=2, N=2048, F=1024, H=16, DH=64, MLP=4096.  T = B*N = 4096 tokens.
// ----------------------------------------------------------------------------

#define T_TOK   4096
#define FDIM    1024
#define NHEAD   16
#define DHEAD   64
#define MLPDIM  4096
#define SEQ     2048
#define LN_EPS  1e-5f

// Scratch (device globals: allocation-free per harness rules)
__device__ float g_h   [(size_t)T_TOK * FDIM];   // LN1 out, reused for LN2 out
__device__ float g_q   [(size_t)T_TOK * FDIM];
__device__ float g_k   [(size_t)T_TOK * FDIM];
__device__ float g_v   [(size_t)T_TOK * FDIM];
__device__ float g_attn[(size_t)T_TOK * FDIM];
__device__ float g_out [(size_t)T_TOK * FDIM];   // residual-1 output
__device__ float g_m1  [(size_t)T_TOK * MLPDIM];

// ---------------------------------------------------------------- LayerNorm
__global__ void ln_kernel(const float* __restrict__ x,
                          const float* __restrict__ g,
                          const float* __restrict__ b,
                          float* __restrict__ y)
{
    __shared__ float red[16];
    const int row = blockIdx.x;
    const int tid = threadIdx.x;                 // 256 threads, 4 floats each
    const float4 v = reinterpret_cast<const float4*>(x + (size_t)row * FDIM)[tid];

    float s  = v.x + v.y + v.z + v.w;
    float s2 = v.x*v.x + v.y*v.y + v.z*v.z + v.w*v.w;
#pragma unroll
    for (int off = 16; off > 0; off >>= 1) {
        s  += __shfl_xor_sync(0xffffffffu, s,  off);
        s2 += __shfl_xor_sync(0xffffffffu, s2, off);
    }
    const int warp = tid >> 5, lane = tid & 31;
    if (lane == 0) { red[warp] = s; red[8 + warp] = s2; }
    __syncthreads();
    float ts = 0.f, ts2 = 0.f;
#pragma unroll
    for (int i = 0; i < 8; i++) { ts += red[i]; ts2 += red[8 + i]; }

    const float mu  = ts * (1.0f / FDIM);
    const float var = ts2 * (1.0f / FDIM) - mu * mu;
    const float inv = rsqrtf(var + LN_EPS);

    const float4 gg = reinterpret_cast<const float4*>(g)[tid];
    const float4 bb = reinterpret_cast<const float4*>(b)[tid];
    float4 o;
    o.x = (v.x - mu) * inv * gg.x + bb.x;
    o.y = (v.y - mu) * inv * gg.y + bb.y;
    o.z = (v.z - mu) * inv * gg.z + bb.z;
    o.w = (v.w - mu) * inv * gg.w + bb.w;
    reinterpret_cast<float4*>(y + (size_t)row * FDIM)[tid] = o;
}

// ---------------------------------------------------------------- SGEMM
// C[M,N] = A[M,K] @ B[K,N] + bias, optional GELU, optional residual add.
// All of M, N divisible by 128; K divisible by 8. 128x128x8 tile, 256 threads,
// 8x8 per-thread microtile.
enum { EPI_BIAS = 0, EPI_BIAS_GELU = 1, EPI_BIAS_RES = 2, EPI_BIAS_GELU_RES = 3 };

__device__ __forceinline__ float gelu_exact(float x) {
    return 0.5f * x * (1.0f + erff(x * 0.70710678118654752440f));
}

template<int EPI>
__global__ __launch_bounds__(256, 2)
void sgemm_kernel(const float* __restrict__ A, const float* __restrict__ B,
                  const float* __restrict__ bias, const float* __restrict__ res,
                  float* __restrict__ C, int M, int N, int K)
{
    __shared__ float As[8][128];
    __shared__ float Bs[8][128];

    const int bx = blockIdx.x, by = blockIdx.y;
    const int tid = threadIdx.x;

    const int aRow = tid >> 1;            // 0..127
    const int aCol = (tid & 1) * 4;       // 0 or 4
    const int bRow = tid >> 5;            // 0..7
    const int bCol = (tid & 31) * 4;      // 0..124

    const float* Ablk = A + (size_t)(by * 128) * K;
    const float* Bblk = B + bx * 128;

    const int tr = (tid >> 4) * 8;        // 0..120
    const int tc = (tid & 15) * 8;        // 0..120

    float acc[8][8] = {};

    for (int k0 = 0; k0 < K; k0 += 8) {
        const float4 a4 = *reinterpret_cast<const float4*>(Ablk + (size_t)aRow * K + k0 + aCol);
        As[aCol + 0][aRow] = a4.x;
        As[aCol + 1][aRow] = a4.y;
        As[aCol + 2][aRow] = a4.z;
        As[aCol + 3][aRow] = a4.w;
        *reinterpret_cast<float4*>(&Bs[bRow][bCol]) =
            *reinterpret_cast<const float4*>(Bblk + (size_t)(k0 + bRow) * N + bCol);
        __syncthreads();

#pragma unroll
        for (int kk = 0; kk < 8; kk++) {
            float ar[8], br[8];
#pragma unroll
            for (int i = 0; i < 8; i++) ar[i] = As[kk][tr + i];
#pragma unroll
            for (int j = 0; j < 8; j++) br[j] = Bs[kk][tc + j];
#pragma unroll
            for (int i = 0; i < 8; i++)
#pragma unroll
                for (int j = 0; j < 8; j++)
                    acc[i][j] = fmaf(ar[i], br[j], acc[i][j]);
        }
        __syncthreads();
    }

    // Epilogue
    const int colBase = bx * 128 + tc;
    const float4 bias0 = *reinterpret_cast<const float4*>(bias + colBase);
    const float4 bias1 = *reinterpret_cast<const float4*>(bias + colBase + 4);

#pragma unroll
    for (int i = 0; i < 8; i++) {
        const int row = by * 128 + tr + i;
        const size_t coff = (size_t)row * N + colBase;
        float4 r0, r1;
        r0.x = acc[i][0] + bias0.x; r0.y = acc[i][1] + bias0.y;
        r0.z = acc[i][2] + bias0.z; r0.w = acc[i][3] + bias0.w;
        r1.x = acc[i][4] + bias1.x; r1.y = acc[i][5] + bias1.y;
        r1.z = acc[i][6] + bias1.z; r1.w = acc[i][7] + bias1.w;
        if (EPI == EPI_BIAS_GELU || EPI == EPI_BIAS_GELU_RES) {
            r0.x = gelu_exact(r0.x); r0.y = gelu_exact(r0.y);
            r0.z = gelu_exact(r0.z); r0.w = gelu_exact(r0.w);
            r1.x = gelu_exact(r1.x); r1.y = gelu_exact(r1.y);
            r1.z = gelu_exact(r1.z); r1.w = gelu_exact(r1.w);
        }
        if (EPI == EPI_BIAS_RES || EPI == EPI_BIAS_GELU_RES) {
            const float4 e0 = *reinterpret_cast<const float4*>(res + coff);
            const float4 e1 = *reinterpret_cast<const float4*>(res + coff + 4);
            r0.x += e0.x; r0.y += e0.y; r0.z += e0.z; r0.w += e0.w;
            r1.x += e1.x; r1.y += e1.y; r1.z += e1.z; r1.w += e1.w;
        }
        *reinterpret_cast<float4*>(C + coff)     = r0;
        *reinterpret_cast<float4*>(C + coff + 4) = r1;
    }
}

// ---------------------------------------------------------------- Attention
// Flash-style, fp32. Each thread owns one query row (q and o in registers).
// grid = (B*H, SEQ/128), block = 128 threads. Off-by-one softmax:
// denom = sum_j exp(a_j - m) + exp(0 - m); slim[h] folded into final scale.
__global__ __launch_bounds__(128)
void attn_kernel(const float* __restrict__ slim)
{
    __shared__ float4 Ks[512];  // 32 keys x 16 float4 (64 floats)
    __shared__ float4 Vs[512];

    const int bh  = blockIdx.x;
    const int b   = bh >> 4;
    const int h   = bh & 15;
    const int tid = threadIdx.x;
    const int t   = b * SEQ + blockIdx.y * 128 + tid;   // global token of my query row

    const float4* qp = reinterpret_cast<const float4*>(g_q + (size_t)t * FDIM + h * DHEAD);
    float4 q[16];
#pragma unroll
    for (int i = 0; i < 16; i++) {
        float4 u = qp[i];
        q[i] = make_float4(u.x * 0.125f, u.y * 0.125f, u.z * 0.125f, u.w * 0.125f);
    }
    float4 o[16];
#pragma unroll
    for (int i = 0; i < 16; i++) o[i] = make_float4(0.f, 0.f, 0.f, 0.f);

    float mrun = -1e30f, srun = 0.f;

#pragma unroll 1
    for (int j0 = 0; j0 < SEQ; j0 += 32) {
        __syncthreads();
#pragma unroll
        for (int i = 0; i < 4; i++) {
            const int f  = tid + i * 128;                  // 0..511
            const int kr = f >> 4, c = f & 15;
            const size_t src = (size_t)(b * SEQ + j0 + kr) * FDIM + h * DHEAD;
            Ks[f] = reinterpret_cast<const float4*>(g_k + src)[c];
            Vs[f] = reinterpret_cast<const float4*>(g_v + src)[c];
        }
        __syncthreads();

#pragma unroll 1
        for (int jj = 0; jj < 32; jj++) {
            const float4* kr = &Ks[jj * 16];
            float s0 = 0.f, s1 = 0.f, s2 = 0.f, s3 = 0.f;
#pragma unroll
            for (int d = 0; d < 16; d += 4) {
                const float4 k0 = kr[d], k1 = kr[d + 1], k2 = kr[d + 2], k3 = kr[d + 3];
                s0 += q[d].x   * k0.x + q[d].y   * k0.y + q[d].z   * k0.z + q[d].w   * k0.w;
                s1 += q[d+1].x * k1.x + q[d+1].y * k1.y + q[d+1].z * k1.z + q[d+1].w * k1.w;
                s2 += q[d+2].x * k2.x + q[d+2].y * k2.y + q[d+2].z * k2.z + q[d+2].w * k2.w;
                s3 += q[d+3].x * k3.x + q[d+3].y * k3.y + q[d+3].z * k3.z + q[d+3].w * k3.w;
            }
            const float s = (s0 + s1) + (s2 + s3);

            const float mnew  = fmaxf(mrun, s);
            const float corr  = __expf(mrun - mnew);
            const float p     = __expf(s - mnew);
            srun = srun * corr + p;
            mrun = mnew;

            const float4* vr = &Vs[jj * 16];
#pragma unroll
            for (int d = 0; d < 16; d++) {
                const float4 vv = vr[d];
                o[d].x = fmaf(o[d].x, corr, p * vv.x);
                o[d].y = fmaf(o[d].y, corr, p * vv.y);
                o[d].z = fmaf(o[d].z, corr, p * vv.z);
                o[d].w = fmaf(o[d].w, corr, p * vv.w);
            }
        }
    }

    // off-by-one denominator: + exp(0 - mrun)
    const float denom = srun + __expf(-mrun);
    const float w = slim[h] / denom;

    float4* op = reinterpret_cast<float4*>(g_attn + (size_t)t * FDIM + h * DHEAD);
#pragma unroll
    for (int d = 0; d < 16; d++)
        op[d] = make_float4(o[d].x * w, o[d].y * w, o[d].z * w, o[d].w * w);
}

// ---------------------------------------------------------------- launch
static float* sym_addr(const void* symbol)
{
    void* p = nullptr;
    cudaGetSymbolAddress(&p, symbol);
    return reinterpret_cast<float*>(p);
}

extern "C" void kernel_launch(void* const* d_in, const int* in_sizes, int n_in,
                              void* d_out, int out_size)
{
    const float* x     = (const float*)d_in[0];
    const float* ln1_g = (const float*)d_in[1];
    const float* ln1_b = (const float*)d_in[2];
    const float* Wq    = (const float*)d_in[3];
    const float* bq    = (const float*)d_in[4];
    const float* Wk    = (const float*)d_in[5];
    const float* bk    = (const float*)d_in[6];
    const float* Wv    = (const float*)d_in[7];
    const float* bv    = (const float*)d_in[8];
    const float* Wo    = (const float*)d_in[9];
    const float* bo    = (const float*)d_in[10];
    const float* slim  = (const float*)d_in[11];
    const float* ln2_g = (const float*)d_in[12];
    const float* ln2_b = (const float*)d_in[13];
    const float* W1    = (const float*)d_in[14];
    const float* b1    = (const float*)d_in[15];
    const float* W2    = (const float*)d_in[16];
    const float* b2    = (const float*)d_in[17];
    float* out = (float*)d_out;

    float* h_p    = sym_addr(g_h);
    float* q_p    = sym_addr(g_q);
    float* k_p    = sym_addr(g_k);
    float* v_p    = sym_addr(g_v);
    float* attn_p = sym_addr(g_attn);
    float* out_p  = sym_addr(g_out);
    float* m1_p   = sym_addr(g_m1);

    const dim3 blk256(256);
    const dim3 gridF(FDIM / 128, T_TOK / 128);     // N=1024 GEMMs
    const dim3 gridM(MLPDIM / 128, T_TOK / 128);   // N=4096 GEMM (W1)

    // 1) LN1
    ln_kernel<<<T_TOK, blk256>>>(x, ln1_g, ln1_b, h_p);

    // 2) QKV projections
    sgemm_kernel<EPI_BIAS><<<gridF, blk256>>>(h_p, Wq, bq, nullptr, q_p, T_TOK, FDIM, FDIM);
    sgemm_kernel<EPI_BIAS><<<gridF, blk256>>>(h_p, Wk, bk, nullptr, k_p, T_TOK, FDIM, FDIM);
    sgemm_kernel<EPI_BIAS><<<gridF, blk256>>>(h_p, Wv, bv, nullptr, v_p, T_TOK, FDIM, FDIM);

    // 3) Attention (flash, off-by-one softmax, slimming)
    attn_kernel<<<dim3(2 * NHEAD, SEQ / 128), dim3(128)>>>(slim);

    // 4) Output projection + residual 1
    sgemm_kernel<EPI_BIAS_RES><<<gridF, blk256>>>(attn_p, Wo, bo, x, out_p, T_TOK, FDIM, FDIM);

    // 5) LN2
    ln_kernel<<<T_TOK, blk256>>>(out_p, ln2_g, ln2_b, h_p);

    // 6) MLP
    sgemm_kernel<EPI_BIAS_GELU><<<gridM, blk256>>>(h_p, W1, b1, nullptr, m1_p, T_TOK, MLPDIM, FDIM);
    sgemm_kernel<EPI_BIAS_GELU_RES><<<gridF, blk256>>>(m1_p, W2, b2, out_p, out, T_TOK, FDIM, MLPDIM);
}

// round 6
// speedup vs baseline: 2.8569x; 2.8569x over previous
#include <cuda_runtime.h>
#include <cuda_bf16.h>
#include <math.h>
#include <stdint.h>

using bf16 = __nv_bfloat16;
#define TT 4096
#define SEQL 2048
#define FDIM 1024
#define DHEAD 64
#define MLPD 4096
#define LN_EPS 1e-5f

// scratch
__device__ bf16 g_h_hi[(size_t)TT*FDIM],  g_h_lo[(size_t)TT*FDIM];
__device__ bf16 g_q_hi[(size_t)TT*FDIM],  g_q_lo[(size_t)TT*FDIM];
__device__ bf16 g_k_hi[(size_t)TT*FDIM],  g_k_lo[(size_t)TT*FDIM];
__device__ bf16 g_vt_hi[(size_t)TT*FDIM], g_vt_lo[(size_t)TT*FDIM];
__device__ bf16 g_at_hi[(size_t)TT*FDIM], g_at_lo[(size_t)TT*FDIM];
__device__ bf16 g_m1_hi[(size_t)TT*MLPD], g_m1_lo[(size_t)TT*MLPD];
__device__ float g_out1[(size_t)TT*FDIM];
__device__ float g_S[(size_t)32*SEQL*SEQL];
__device__ bf16  g_P[(size_t)32*SEQL*SEQL];
__device__ bf16 g_wq_hi[(size_t)FDIM*FDIM], g_wq_lo[(size_t)FDIM*FDIM];
__device__ bf16 g_wk_hi[(size_t)FDIM*FDIM], g_wk_lo[(size_t)FDIM*FDIM];
__device__ bf16 g_wv_hi[(size_t)FDIM*FDIM], g_wv_lo[(size_t)FDIM*FDIM];
__device__ bf16 g_wo_hi[(size_t)FDIM*FDIM], g_wo_lo[(size_t)FDIM*FDIM];
__device__ bf16 g_w1_hi[(size_t)FDIM*MLPD], g_w1_lo[(size_t)FDIM*MLPD];
__device__ bf16 g_w2_hi[(size_t)FDIM*MLPD], g_w2_lo[(size_t)FDIM*MLPD];

__device__ __forceinline__ uint32_t smem_u32(const void* p){
    uint32_t a; asm("{ .reg .u64 t; cvta.to.shared.u64 t,%1; cvt.u32.u64 %0,t; }":"=r"(a):"l"(p)); return a;
}
__device__ __forceinline__ uint32_t lds32(uint32_t a){
    uint32_t v; asm volatile("ld.shared.b32 %0,[%1];":"=r"(v):"r"(a)); return v;
}
__device__ __forceinline__ uint32_t pk(float a,float b){
    return ((uint32_t)__bfloat16_as_ushort(__float2bfloat16(b))<<16)|__bfloat16_as_ushort(__float2bfloat16(a));
}
__device__ __forceinline__ float gelu_exact(float x){ return 0.5f*x*(1.0f+erff(x*0.70710678118654752440f)); }

__device__ __forceinline__ void mma16816(float* c, uint32_t a0,uint32_t a1,uint32_t a2,uint32_t a3,
                                         uint32_t b0,uint32_t b1){
    asm volatile("mma.sync.aligned.m16n8k16.row.col.f32.bf16.bf16.f32 "
        "{%0,%1,%2,%3},{%4,%5,%6,%7},{%8,%9},{%0,%1,%2,%3};"
        : "+f"(c[0]),"+f"(c[1]),"+f"(c[2]),"+f"(c[3])
        : "r"(a0),"r"(a1),"r"(a2),"r"(a3),"r"(b0),"r"(b1));
}

// cp.async a R x 32 bf16 tile into smem with 80B row stride (64B data + 16B pad)
template<int R>
__device__ __forceinline__ void cpa(uint32_t dst, const bf16* __restrict__ src, int ldk, int tid){
#pragma unroll
    for(int it=0; it<R*4/256; ++it){
        const int u=tid+it*256, r=u>>2, ch=u&3;
        const uint32_t d = dst + r*80 + ch*16;
        const void* g = src + (size_t)r*ldk + ch*8;
        asm volatile("cp.async.cg.shared.global [%0], [%1], 16;\n"::"r"(d),"l"(g));
    }
}
#define CP_COMMIT() asm volatile("cp.async.commit_group;")
#define CP_WAIT(n)  asm volatile("cp.async.wait_group %0;"::"n"(n))

enum { EPI_QK=0, EPI_V=1, EPI_S=2, EPI_PV=3, EPI_WO=4, EPI_W1=5, EPI_W2=6 };

// C[128 x TILE_N] = A[128,K] * B[TILE_N,K]^T (both K-major bf16 hi/lo).
// TERMS=3: Ah*Bh + Ah*Bl + Al*Bh.  TERMS=2: Ah*Bh + Ah*Bl.
template<int TILE_N,int TERMS,int EPI>
__global__ __launch_bounds__(256)
void gemm_mma(const bf16* __restrict__ Ahi, const bf16* __restrict__ Alo,
              const bf16* __restrict__ Bhi, const bf16* __restrict__ Blo,
              int K, size_t sA, size_t sB,
              const float* __restrict__ bias, const float* __restrict__ res,
              float* __restrict__ outf, bf16* __restrict__ ohi, bf16* __restrict__ olo)
{
    constexpr int ASZ=128*80, BSZ=TILE_N*80;
    constexpr int NA=(TERMS==3)?2:1;
    constexpr int BUFSZ=NA*ASZ+2*BSZ;
    constexpr int WN=TILE_N/2, NT=TILE_N/16;
    extern __shared__ char sm[];
    const uint32_t sb=smem_u32(sm);
    const int tid=threadIdx.x, warp=tid>>5, lane=tid&31;
    const int wm=warp>>1, wn=warp&1;

    const size_t zA=(size_t)blockIdx.z*sA, zB=(size_t)blockIdx.z*sB;
    const int mrow0=blockIdx.y*128, ncol0=blockIdx.x*TILE_N;
    const bf16* Ah=Ahi+zA+(size_t)mrow0*K;
    const bf16* Al=(TERMS==3)?(Alo+zA+(size_t)mrow0*K):nullptr;
    const bf16* Bh=Bhi+zB+(size_t)ncol0*K;
    const bf16* Bl=Blo+zB+(size_t)ncol0*K;

    float acc[2][NT][4];
#pragma unroll
    for(int i=0;i<2;i++)
#pragma unroll
        for(int j=0;j<NT;j++){ acc[i][j][0]=0.f;acc[i][j][1]=0.f;acc[i][j][2]=0.f;acc[i][j][3]=0.f; }

    const int NC=K>>5;
    // prologue: chunk 0
    {
        const uint32_t b0=sb;
        cpa<128>(b0, Ah, K, tid);
        if(TERMS==3) cpa<128>(b0+ASZ, Al, K, tid);
        cpa<TILE_N>(b0+NA*ASZ, Bh, K, tid);
        cpa<TILE_N>(b0+NA*ASZ+BSZ, Bl, K, tid);
        CP_COMMIT();
    }
    for(int c=0;c<NC;c++){
        if(c+1<NC){
            const int k0=(c+1)<<5;
            const uint32_t bs=sb+((c+1)&1)*BUFSZ;
            cpa<128>(bs, Ah+k0, K, tid);
            if(TERMS==3) cpa<128>(bs+ASZ, Al+k0, K, tid);
            cpa<TILE_N>(bs+NA*ASZ, Bh+k0, K, tid);
            cpa<TILE_N>(bs+NA*ASZ+BSZ, Bl+k0, K, tid);
            CP_COMMIT();
            CP_WAIT(1);
        } else {
            CP_WAIT(0);
        }
        __syncthreads();
        const uint32_t base=sb+(c&1)*BUFSZ;
        const uint32_t aHb=base, aLb=base+ASZ;
        const uint32_t bHb=base+NA*ASZ, bLb=base+NA*ASZ+BSZ;
        const int gr=lane>>2, tc=lane&3;
#pragma unroll
        for(int ks=0;ks<2;ks++){
            const int cu=tc+8*ks;
            uint32_t ah[2][4], al[2][4], bh[NT][2], bl[NT][2];
#pragma unroll
            for(int mt=0;mt<2;mt++){
                const int r=wm*32+mt*16+gr;
                ah[mt][0]=lds32(aHb+r*80+cu*4);
                ah[mt][1]=lds32(aHb+(r+8)*80+cu*4);
                ah[mt][2]=lds32(aHb+r*80+(cu+4)*4);
                ah[mt][3]=lds32(aHb+(r+8)*80+(cu+4)*4);
                if(TERMS==3){
                    al[mt][0]=lds32(aLb+r*80+cu*4);
                    al[mt][1]=lds32(aLb+(r+8)*80+cu*4);
                    al[mt][2]=lds32(aLb+r*80+(cu+4)*4);
                    al[mt][3]=lds32(aLb+(r+8)*80+(cu+4)*4);
                }
            }
#pragma unroll
            for(int nt=0;nt<NT;nt++){
                const int n=wn*WN+nt*8+gr;
                bh[nt][0]=lds32(bHb+n*80+cu*4);
                bh[nt][1]=lds32(bHb+n*80+(cu+4)*4);
                bl[nt][0]=lds32(bLb+n*80+cu*4);
                bl[nt][1]=lds32(bLb+n*80+(cu+4)*4);
            }
#pragma unroll
            for(int mt=0;mt<2;mt++)
#pragma unroll
                for(int nt=0;nt<NT;nt++)
                    mma16816(acc[mt][nt], ah[mt][0],ah[mt][1],ah[mt][2],ah[mt][3], bh[nt][0],bh[nt][1]);
#pragma unroll
            for(int mt=0;mt<2;mt++)
#pragma unroll
                for(int nt=0;nt<NT;nt++)
                    mma16816(acc[mt][nt], ah[mt][0],ah[mt][1],ah[mt][2],ah[mt][3], bl[nt][0],bl[nt][1]);
            if(TERMS==3){
#pragma unroll
                for(int mt=0;mt<2;mt++)
#pragma unroll
                    for(int nt=0;nt<NT;nt++)
                        mma16816(acc[mt][nt], al[mt][0],al[mt][1],al[mt][2],al[mt][3], bh[nt][0],bh[nt][1]);
            }
        }
        __syncthreads();
    }

    // ---------------- epilogue ----------------
    const int gr=lane>>2, tc=lane&3;
#pragma unroll
    for(int mt=0;mt<2;mt++)
#pragma unroll
    for(int hf=0;hf<2;hf++){
        const int grow=mrow0+wm*32+mt*16+gr+8*hf;
#pragma unroll
        for(int nt=0;nt<NT;nt++){
            const int col=ncol0+wn*WN+nt*8+2*tc;
            float v0=acc[mt][nt][2*hf], v1=acc[mt][nt][2*hf+1];
            if(EPI==EPI_QK||EPI==EPI_V||EPI==EPI_WO||EPI==EPI_W1||EPI==EPI_W2){
                const float2 bb=__ldg(reinterpret_cast<const float2*>(bias+col));
                v0+=bb.x; v1+=bb.y;
            }
            if(EPI==EPI_W1||EPI==EPI_W2){ v0=gelu_exact(v0); v1=gelu_exact(v1); }
            if(EPI==EPI_WO||EPI==EPI_W2){
                const float2 rr=__ldg(reinterpret_cast<const float2*>(res+(size_t)grow*FDIM+col));
                v0+=rr.x; v1+=rr.y;
            }
            if(EPI==EPI_QK){
                const int b=grow>>11, i=grow&2047, h=col>>6, d=col&63;
                const size_t dst=((size_t)((b<<4)+h)*SEQL+i)*DHEAD+d;
                const float h0=__bfloat162float(__float2bfloat16(v0));
                const float h1=__bfloat162float(__float2bfloat16(v1));
                *reinterpret_cast<uint32_t*>(ohi+dst)=pk(v0,v1);
                *reinterpret_cast<uint32_t*>(olo+dst)=pk(v0-h0,v1-h1);
            } else if(EPI==EPI_V){
                const int b=grow>>11, i=grow&2047, h=col>>6, d=col&63;
                const size_t base0=((size_t)((b<<4)+h)*DHEAD+d)*SEQL+i;
                const bf16 h0=__float2bfloat16(v0), h1=__float2bfloat16(v1);
                ohi[base0]=h0; olo[base0]=__float2bfloat16(v0-__bfloat162float(h0));
                ohi[base0+SEQL]=h1; olo[base0+SEQL]=__float2bfloat16(v1-__bfloat162float(h1));
            } else if(EPI==EPI_S){
                float2 o; o.x=v0*0.125f; o.y=v1*0.125f;
                *reinterpret_cast<float2*>(outf+((size_t)blockIdx.z*SEQL+grow)*SEQL+col)=o;
            } else if(EPI==EPI_PV){
                const int b=blockIdx.z>>4, h=blockIdx.z&15;
                const size_t dst=((size_t)(b*SEQL+grow))*FDIM+h*DHEAD+col;
                const float h0=__bfloat162float(__float2bfloat16(v0));
                const float h1=__bfloat162float(__float2bfloat16(v1));
                *reinterpret_cast<uint32_t*>(ohi+dst)=pk(v0,v1);
                *reinterpret_cast<uint32_t*>(olo+dst)=pk(v0-h0,v1-h1);
            } else if(EPI==EPI_WO||EPI==EPI_W2){
                float2 o; o.x=v0; o.y=v1;
                *reinterpret_cast<float2*>(outf+(size_t)grow*FDIM+col)=o;
            } else if(EPI==EPI_W1){
                const size_t dst=(size_t)grow*MLPD+col;
                const float h0=__bfloat162float(__float2bfloat16(v0));
                const float h1=__bfloat162float(__float2bfloat16(v1));
                *reinterpret_cast<uint32_t*>(ohi+dst)=pk(v0,v1);
                *reinterpret_cast<uint32_t*>(olo+dst)=pk(v0-h0,v1-h1);
            }
        }
    }
}

__global__ __launch_bounds__(256)
void ln_kernel(const float* __restrict__ x, const float* __restrict__ g,
               const float* __restrict__ b, bf16* __restrict__ yhi, bf16* __restrict__ ylo)
{
    __shared__ float red[16];
    const int row=blockIdx.x, tid=threadIdx.x;
    const float4 v=reinterpret_cast<const float4*>(x+(size_t)row*FDIM)[tid];
    float s=v.x+v.y+v.z+v.w, s2=v.x*v.x+v.y*v.y+v.z*v.z+v.w*v.w;
#pragma unroll
    for(int o=16;o>0;o>>=1){ s+=__shfl_xor_sync(~0u,s,o); s2+=__shfl_xor_sync(~0u,s2,o); }
    const int warp=tid>>5, lane=tid&31;
    if(lane==0){ red[warp]=s; red[8+warp]=s2; }
    __syncthreads();
    float ts=0.f, ts2=0.f;
#pragma unroll
    for(int i=0;i<8;i++){ ts+=red[i]; ts2+=red[8+i]; }
    const float mu=ts*(1.f/FDIM), var=ts2*(1.f/FDIM)-mu*mu, inv=rsqrtf(var+LN_EPS);
    const float4 gg=reinterpret_cast<const float4*>(g)[tid];
    const float4 bb=reinterpret_cast<const float4*>(b)[tid];
    const float o0=(v.x-mu)*inv*gg.x+bb.x, o1=(v.y-mu)*inv*gg.y+bb.y;
    const float o2=(v.z-mu)*inv*gg.z+bb.z, o3=(v.w-mu)*inv*gg.w+bb.w;
    const float h0=__bfloat162float(__float2bfloat16(o0)), h1=__bfloat162float(__float2bfloat16(o1));
    const float h2=__bfloat162float(__float2bfloat16(o2)), h3=__bfloat162float(__float2bfloat16(o3));
    uint2 H,L;
    H.x=pk(o0,o1); H.y=pk(o2,o3);
    L.x=pk(o0-h0,o1-h1); L.y=pk(o2-h2,o3-h3);
    const size_t dst=(size_t)row*FDIM+tid*4;
    *reinterpret_cast<uint2*>(yhi+dst)=H;
    *reinterpret_cast<uint2*>(ylo+dst)=L;
}

__global__ __launch_bounds__(256)
void wconv_kernel(const float* __restrict__ W, bf16* __restrict__ hi, bf16* __restrict__ lo, int K, int N)
{
    __shared__ float s[32][33];
    const int n0=blockIdx.x*32, k0=blockIdx.y*32;
    const int tx=threadIdx.x, ty=threadIdx.y;
#pragma unroll
    for(int j=0;j<4;j++) s[ty+8*j][tx]=W[(size_t)(k0+ty+8*j)*N+n0+tx];
    __syncthreads();
#pragma unroll
    for(int j=0;j<4;j++){
        const float v=s[tx][ty+8*j];
        const bf16 h=__float2bfloat16(v);
        const size_t dst=(size_t)(n0+ty+8*j)*K+k0+tx;
        hi[dst]=h; lo[dst]=__float2bfloat16(v-__bfloat162float(h));
    }
}

__global__ __launch_bounds__(256)
void softmax_kernel(const float* __restrict__ S, bf16* __restrict__ P, const float* __restrict__ slim)
{
    __shared__ float red[16];
    const int i=blockIdx.x, bh=blockIdx.y, h=bh&15;
    const float* row=S+((size_t)bh*SEQL+i)*SEQL;
    const int tid=threadIdx.x, warp=tid>>5, lane=tid&31;
    float a[8];
    { const float4 u0=__ldg(reinterpret_cast<const float4*>(row)+tid*2);
      const float4 u1=__ldg(reinterpret_cast<const float4*>(row)+tid*2+1);
      a[0]=u0.x;a[1]=u0.y;a[2]=u0.z;a[3]=u0.w;a[4]=u1.x;a[5]=u1.y;a[6]=u1.z;a[7]=u1.w; }
    float m=a[0];
#pragma unroll
    for(int j=1;j<8;j++) m=fmaxf(m,a[j]);
#pragma unroll
    for(int o=16;o>0;o>>=1) m=fmaxf(m,__shfl_xor_sync(~0u,m,o));
    if(lane==0) red[warp]=m;
    __syncthreads();
    float M=red[0];
#pragma unroll
    for(int j=1;j<8;j++) M=fmaxf(M,red[j]);
    float e[8], sum=0.f;
#pragma unroll
    for(int j=0;j<8;j++){ e[j]=__expf(a[j]-M); sum+=e[j]; }
#pragma unroll
    for(int o=16;o>0;o>>=1) sum+=__shfl_xor_sync(~0u,sum,o);
    if(lane==0) red[8+warp]=sum;
    __syncthreads();
    float tot=0.f;
#pragma unroll
    for(int j=0;j<8;j++) tot+=red[8+j];
    const float scale=__ldg(slim+h)/(1.0f+tot);
    union{uint4 u; ushort s[8];} O;
#pragma unroll
    for(int j=0;j<8;j++) O.s[j]=__bfloat16_as_ushort(__float2bfloat16(e[j]*scale));
    *reinterpret_cast<uint4*>(P+((size_t)bh*SEQL+i)*SEQL+tid*8)=O.u;
}

static void* sym_addr(const void* s){ void* p=nullptr; cudaGetSymbolAddress(&p,s); return p; }

extern "C" void kernel_launch(void* const* d_in, const int* in_sizes, int n_in,
                              void* d_out, int out_size)
{
    const float* x=(const float*)d_in[0];
    const float* ln1_g=(const float*)d_in[1]; const float* ln1_b=(const float*)d_in[2];
    const float* Wq=(const float*)d_in[3];  const float* bq=(const float*)d_in[4];
    const float* Wk=(const float*)d_in[5];  const float* bk=(const float*)d_in[6];
    const float* Wv=(const float*)d_in[7];  const float* bv=(const float*)d_in[8];
    const float* Wo=(const float*)d_in[9];  const float* bo=(const float*)d_in[10];
    const float* slim=(const float*)d_in[11];
    const float* ln2_g=(const float*)d_in[12]; const float* ln2_b=(const float*)d_in[13];
    const float* W1=(const float*)d_in[14]; const float* b1=(const float*)d_in[15];
    const float* W2=(const float*)d_in[16]; const float* b2=(const float*)d_in[17];
    float* out=(float*)d_out;

    bf16 *h_hi=(bf16*)sym_addr(g_h_hi), *h_lo=(bf16*)sym_addr(g_h_lo);
    bf16 *q_hi=(bf16*)sym_addr(g_q_hi), *q_lo=(bf16*)sym_addr(g_q_lo);
    bf16 *k_hi=(bf16*)sym_addr(g_k_hi), *k_lo=(bf16*)sym_addr(g_k_lo);
    bf16 *vt_hi=(bf16*)sym_addr(g_vt_hi), *vt_lo=(bf16*)sym_addr(g_vt_lo);
    bf16 *at_hi=(bf16*)sym_addr(g_at_hi), *at_lo=(bf16*)sym_addr(g_at_lo);
    bf16 *m1_hi=(bf16*)sym_addr(g_m1_hi), *m1_lo=(bf16*)sym_addr(g_m1_lo);
    float* out1=(float*)sym_addr(g_out1);
    float* Sp=(float*)sym_addr(g_S); bf16* Pp=(bf16*)sym_addr(g_P);
    bf16 *wqh=(bf16*)sym_addr(g_wq_hi), *wql=(bf16*)sym_addr(g_wq_lo);
    bf16 *wkh=(bf16*)sym_addr(g_wk_hi), *wkl=(bf16*)sym_addr(g_wk_lo);
    bf16 *wvh=(bf16*)sym_addr(g_wv_hi), *wvl=(bf16*)sym_addr(g_wv_lo);
    bf16 *woh=(bf16*)sym_addr(g_wo_hi), *wol=(bf16*)sym_addr(g_wo_lo);
    bf16 *w1h=(bf16*)sym_addr(g_w1_hi), *w1l=(bf16*)sym_addr(g_w1_lo);
    bf16 *w2h=(bf16*)sym_addr(g_w2_hi), *w2l=(bf16*)sym_addr(g_w2_lo);

    // smem: T3/N128: 2*(2*10240 + 2*10240) = 81920 ; T2/N64: 2*(10240 + 2*5120) = 40960
    constexpr int SM3=81920, SM2=40960;
    cudaFuncSetAttribute(gemm_mma<128,3,EPI_QK>, cudaFuncAttributeMaxDynamicSharedMemorySize, SM3);
    cudaFuncSetAttribute(gemm_mma<128,3,EPI_V >, cudaFuncAttributeMaxDynamicSharedMemorySize, SM3);
    cudaFuncSetAttribute(gemm_mma<128,3,EPI_S >, cudaFuncAttributeMaxDynamicSharedMemorySize, SM3);
    cudaFuncSetAttribute(gemm_mma<64 ,2,EPI_PV>, cudaFuncAttributeMaxDynamicSharedMemorySize, SM2);
    cudaFuncSetAttribute(gemm_mma<128,3,EPI_WO>, cudaFuncAttributeMaxDynamicSharedMemorySize, SM3);
    cudaFuncSetAttribute(gemm_mma<128,3,EPI_W1>, cudaFuncAttributeMaxDynamicSharedMemorySize, SM3);
    cudaFuncSetAttribute(gemm_mma<128,3,EPI_W2>, cudaFuncAttributeMaxDynamicSharedMemorySize, SM3);

    const dim3 wb(32,8);
    wconv_kernel<<<dim3(FDIM/32,FDIM/32),wb>>>(Wq,wqh,wql,FDIM,FDIM);
    wconv_kernel<<<dim3(FDIM/32,FDIM/32),wb>>>(Wk,wkh,wkl,FDIM,FDIM);
    wconv_kernel<<<dim3(FDIM/32,FDIM/32),wb>>>(Wv,wvh,wvl,FDIM,FDIM);
    wconv_kernel<<<dim3(FDIM/32,FDIM/32),wb>>>(Wo,woh,wol,FDIM,FDIM);
    wconv_kernel<<<dim3(MLPD/32,FDIM/32),wb>>>(W1,w1h,w1l,FDIM,MLPD);
    wconv_kernel<<<dim3(FDIM/32,MLPD/32),wb>>>(W2,w2h,w2l,MLPD,FDIM);

    ln_kernel<<<TT,256>>>(x,ln1_g,ln1_b,h_hi,h_lo);

    gemm_mma<128,3,EPI_QK><<<dim3(8,32,1),256,SM3>>>(h_hi,h_lo,wqh,wql,FDIM,0,0,bq,nullptr,nullptr,q_hi,q_lo);
    gemm_mma<128,3,EPI_QK><<<dim3(8,32,1),256,SM3>>>(h_hi,h_lo,wkh,wkl,FDIM,0,0,bk,nullptr,nullptr,k_hi,k_lo);
    gemm_mma<128,3,EPI_V ><<<dim3(8,32,1),256,SM3>>>(h_hi,h_lo,wvh,wvl,FDIM,0,0,bv,nullptr,nullptr,vt_hi,vt_lo);

    // S = QK^T/8 per (b,h): M=N=2048, K=64
    gemm_mma<128,3,EPI_S><<<dim3(16,16,32),256,SM3>>>(q_hi,q_lo,k_hi,k_lo,DHEAD,
        (size_t)SEQL*DHEAD,(size_t)SEQL*DHEAD,nullptr,nullptr,Sp,nullptr,nullptr);

    softmax_kernel<<<dim3(SEQL,32),256>>>(Sp,Pp,slim);

    // attn = P @ V : M=2048, N=64, K=2048 per (b,h)
    gemm_mma<64,2,EPI_PV><<<dim3(1,16,32),256,SM2>>>(Pp,nullptr,vt_hi,vt_lo,SEQL,
        (size_t)SEQL*SEQL,(size_t)DHEAD*SEQL,nullptr,nullptr,nullptr,at_hi,at_lo);

    gemm_mma<128,3,EPI_WO><<<dim3(8,32,1),256,SM3>>>(at_hi,at_lo,woh,wol,FDIM,0,0,bo,x,out1,nullptr,nullptr);

    ln_kernel<<<TT,256>>>(out1,ln2_g,ln2_b,h_hi,h_lo);

    gemm_mma<128,3,EPI_W1><<<dim3(32,32,1),256,SM3>>>(h_hi,h_lo,w1h,w1l,FDIM,0,0,b1,nullptr,nullptr,m1_hi,m1_lo);
    gemm_mma<128,3,EPI_W2><<<dim3(8,32,1),256,SM3>>>(m1_hi,m1_lo,w2h,w2l,MLPD,0,0,b2,out1,out,nullptr,nullptr);
}

// round 7
// speedup vs baseline: 3.2802x; 1.1482x over previous
#include <cuda_runtime.h>
#include <cuda_bf16.h>
#include <math.h>
#include <stdint.h>

using bf16 = __nv_bfloat16;
#define TT 4096
#define SEQL 2048
#define FDIM 1024
#define DHEAD 64
#define MLPD 4096
#define LN_EPS 1e-5f

// scratch
__device__ bf16 g_h_hi[(size_t)TT*FDIM],  g_h_lo[(size_t)TT*FDIM];
__device__ bf16 g_q_hi[(size_t)TT*FDIM],  g_q_lo[(size_t)TT*FDIM];
__device__ bf16 g_k_hi[(size_t)TT*FDIM],  g_k_lo[(size_t)TT*FDIM];
__device__ bf16 g_vt_hi[(size_t)TT*FDIM], g_vt_lo[(size_t)TT*FDIM];
__device__ bf16 g_at_hi[(size_t)TT*FDIM], g_at_lo[(size_t)TT*FDIM];
__device__ bf16 g_m1_hi[(size_t)TT*MLPD], g_m1_lo[(size_t)TT*MLPD];
__device__ float g_out1[(size_t)TT*FDIM];
__device__ bf16 g_wq_hi[(size_t)FDIM*FDIM], g_wq_lo[(size_t)FDIM*FDIM];
__device__ bf16 g_wk_hi[(size_t)FDIM*FDIM], g_wk_lo[(size_t)FDIM*FDIM];
__device__ bf16 g_wv_hi[(size_t)FDIM*FDIM], g_wv_lo[(size_t)FDIM*FDIM];
__device__ bf16 g_wo_hi[(size_t)FDIM*FDIM], g_wo_lo[(size_t)FDIM*FDIM];
__device__ bf16 g_w1_hi[(size_t)FDIM*MLPD], g_w1_lo[(size_t)FDIM*MLPD];
__device__ bf16 g_w2_hi[(size_t)FDIM*MLPD], g_w2_lo[(size_t)FDIM*MLPD];

__device__ __forceinline__ uint32_t smem_u32(const void* p){
    uint32_t a; asm("{ .reg .u64 t; cvta.to.shared.u64 t,%1; cvt.u32.u64 %0,t; }":"=r"(a):"l"(p)); return a;
}
__device__ __forceinline__ uint32_t lds32(uint32_t a){
    uint32_t v; asm volatile("ld.shared.b32 %0,[%1];":"=r"(v):"r"(a)); return v;
}
__device__ __forceinline__ uint32_t pk(float a,float b){
    return ((uint32_t)__bfloat16_as_ushort(__float2bfloat16(b))<<16)|__bfloat16_as_ushort(__float2bfloat16(a));
}
__device__ __forceinline__ float gelu_exact(float x){ return 0.5f*x*(1.0f+erff(x*0.70710678118654752440f)); }

__device__ __forceinline__ void mma16816(float* c, uint32_t a0,uint32_t a1,uint32_t a2,uint32_t a3,
                                         uint32_t b0,uint32_t b1){
    asm volatile("mma.sync.aligned.m16n8k16.row.col.f32.bf16.bf16.f32 "
        "{%0,%1,%2,%3},{%4,%5,%6,%7},{%8,%9},{%0,%1,%2,%3};"
        : "+f"(c[0]),"+f"(c[1]),"+f"(c[2]),"+f"(c[3])
        : "r"(a0),"r"(a1),"r"(a2),"r"(a3),"r"(b0),"r"(b1));
}
__device__ __forceinline__ void cp16(uint32_t d, const void* g){
    asm volatile("cp.async.cg.shared.global [%0], [%1], 16;\n"::"r"(d),"l"(g));
}
// cp.async a R x 32 bf16 tile into smem with 80B row stride (64B data + 16B pad)
template<int R>
__device__ __forceinline__ void cpa(uint32_t dst, const bf16* __restrict__ src, int ldk, int tid){
#pragma unroll
    for(int it=0; it<R*4/256; ++it){
        const int u=tid+it*256, r=u>>2, ch=u&3;
        cp16(dst + r*80 + ch*16, src + (size_t)r*ldk + ch*8);
    }
}
#define CP_COMMIT() asm volatile("cp.async.commit_group;")
#define CP_WAIT(n)  asm volatile("cp.async.wait_group %0;"::"n"(n))

enum { EPI_QK=0, EPI_V=1, EPI_WO=4, EPI_W1=5, EPI_W2=6 };

// C[128 x TILE_N] = A[128,K] * B[TILE_N,K]^T (K-major bf16 hi/lo). TERMS=3: AhBh+AhBl+AlBh.
template<int TILE_N,int TERMS,int EPI>
__global__ __launch_bounds__(256)
void gemm_mma(const bf16* __restrict__ Ahi, const bf16* __restrict__ Alo,
              const bf16* __restrict__ Bhi, const bf16* __restrict__ Blo,
              int K, size_t sA, size_t sB,
              const float* __restrict__ bias, const float* __restrict__ res,
              float* __restrict__ outf, bf16* __restrict__ ohi, bf16* __restrict__ olo)
{
    constexpr int ASZ=128*80, BSZ=TILE_N*80;
    constexpr int NA=(TERMS==3)?2:1;
    constexpr int BUFSZ=NA*ASZ+2*BSZ;
    constexpr int WN=TILE_N/2, NT=TILE_N/16;
    extern __shared__ char sm[];
    const uint32_t sb=smem_u32(sm);
    const int tid=threadIdx.x, warp=tid>>5, lane=tid&31;
    const int wm=warp>>1, wn=warp&1;

    const size_t zA=(size_t)blockIdx.z*sA, zB=(size_t)blockIdx.z*sB;
    const int mrow0=blockIdx.y*128, ncol0=blockIdx.x*TILE_N;
    const bf16* Ah=Ahi+zA+(size_t)mrow0*K;
    const bf16* Al=(TERMS==3)?(Alo+zA+(size_t)mrow0*K):nullptr;
    const bf16* Bh=Bhi+zB+(size_t)ncol0*K;
    const bf16* Bl=Blo+zB+(size_t)ncol0*K;

    float acc[2][NT][4];
#pragma unroll
    for(int i=0;i<2;i++)
#pragma unroll
        for(int j=0;j<NT;j++){ acc[i][j][0]=0.f;acc[i][j][1]=0.f;acc[i][j][2]=0.f;acc[i][j][3]=0.f; }

    const int NC=K>>5;
    {
        cpa<128>(sb, Ah, K, tid);
        if(TERMS==3) cpa<128>(sb+ASZ, Al, K, tid);
        cpa<TILE_N>(sb+NA*ASZ, Bh, K, tid);
        cpa<TILE_N>(sb+NA*ASZ+BSZ, Bl, K, tid);
        CP_COMMIT();
    }
    for(int c=0;c<NC;c++){
        if(c+1<NC){
            const int k0=(c+1)<<5;
            const uint32_t bs=sb+((c+1)&1)*BUFSZ;
            cpa<128>(bs, Ah+k0, K, tid);
            if(TERMS==3) cpa<128>(bs+ASZ, Al+k0, K, tid);
            cpa<TILE_N>(bs+NA*ASZ, Bh+k0, K, tid);
            cpa<TILE_N>(bs+NA*ASZ+BSZ, Bl+k0, K, tid);
            CP_COMMIT();
            CP_WAIT(1);
        } else {
            CP_WAIT(0);
        }
        __syncthreads();
        const uint32_t base=sb+(c&1)*BUFSZ;
        const uint32_t aHb=base, aLb=base+ASZ;
        const uint32_t bHb=base+NA*ASZ, bLb=base+NA*ASZ+BSZ;
        const int gr=lane>>2, tc=lane&3;
#pragma unroll
        for(int ks=0;ks<2;ks++){
            const int cu=tc+8*ks;
            uint32_t ah[2][4], al[2][4], bh[NT][2], bl[NT][2];
#pragma unroll
            for(int mt=0;mt<2;mt++){
                const int r=wm*32+mt*16+gr;
                ah[mt][0]=lds32(aHb+r*80+cu*4);
                ah[mt][1]=lds32(aHb+(r+8)*80+cu*4);
                ah[mt][2]=lds32(aHb+r*80+(cu+4)*4);
                ah[mt][3]=lds32(aHb+(r+8)*80+(cu+4)*4);
                if(TERMS==3){
                    al[mt][0]=lds32(aLb+r*80+cu*4);
                    al[mt][1]=lds32(aLb+(r+8)*80+cu*4);
                    al[mt][2]=lds32(aLb+r*80+(cu+4)*4);
                    al[mt][3]=lds32(aLb+(r+8)*80+(cu+4)*4);
                }
            }
#pragma unroll
            for(int nt=0;nt<NT;nt++){
                const int n=wn*WN+nt*8+gr;
                bh[nt][0]=lds32(bHb+n*80+cu*4);
                bh[nt][1]=lds32(bHb+n*80+(cu+4)*4);
                bl[nt][0]=lds32(bLb+n*80+cu*4);
                bl[nt][1]=lds32(bLb+n*80+(cu+4)*4);
            }
#pragma unroll
            for(int mt=0;mt<2;mt++)
#pragma unroll
                for(int nt=0;nt<NT;nt++)
                    mma16816(acc[mt][nt], ah[mt][0],ah[mt][1],ah[mt][2],ah[mt][3], bh[nt][0],bh[nt][1]);
#pragma unroll
            for(int mt=0;mt<2;mt++)
#pragma unroll
                for(int nt=0;nt<NT;nt++)
                    mma16816(acc[mt][nt], ah[mt][0],ah[mt][1],ah[mt][2],ah[mt][3], bl[nt][0],bl[nt][1]);
            if(TERMS==3){
#pragma unroll
                for(int mt=0;mt<2;mt++)
#pragma unroll
                    for(int nt=0;nt<NT;nt++)
                        mma16816(acc[mt][nt], al[mt][0],al[mt][1],al[mt][2],al[mt][3], bh[nt][0],bh[nt][1]);
            }
        }
        __syncthreads();
    }

    const int gr=lane>>2, tc=lane&3;
#pragma unroll
    for(int mt=0;mt<2;mt++)
#pragma unroll
    for(int hf=0;hf<2;hf++){
        const int grow=mrow0+wm*32+mt*16+gr+8*hf;
#pragma unroll
        for(int nt=0;nt<NT;nt++){
            const int col=ncol0+wn*WN+nt*8+2*tc;
            float v0=acc[mt][nt][2*hf], v1=acc[mt][nt][2*hf+1];
            if(EPI==EPI_QK||EPI==EPI_V||EPI==EPI_WO||EPI==EPI_W1||EPI==EPI_W2){
                const float2 bb=__ldg(reinterpret_cast<const float2*>(bias+col));
                v0+=bb.x; v1+=bb.y;
            }
            if(EPI==EPI_W1||EPI==EPI_W2){ v0=gelu_exact(v0); v1=gelu_exact(v1); }
            if(EPI==EPI_WO||EPI==EPI_W2){
                const float2 rr=__ldg(reinterpret_cast<const float2*>(res+(size_t)grow*FDIM+col));
                v0+=rr.x; v1+=rr.y;
            }
            if(EPI==EPI_QK){
                const int b=grow>>11, i=grow&2047, h=col>>6, d=col&63;
                const size_t dst=((size_t)((b<<4)+h)*SEQL+i)*DHEAD+d;
                const float h0=__bfloat162float(__float2bfloat16(v0));
                const float h1=__bfloat162float(__float2bfloat16(v1));
                *reinterpret_cast<uint32_t*>(ohi+dst)=pk(v0,v1);
                *reinterpret_cast<uint32_t*>(olo+dst)=pk(v0-h0,v1-h1);
            } else if(EPI==EPI_V){
                const int b=grow>>11, i=grow&2047, h=col>>6, d=col&63;
                const size_t base0=((size_t)((b<<4)+h)*DHEAD+d)*SEQL+i;
                const bf16 h0=__float2bfloat16(v0), h1=__float2bfloat16(v1);
                ohi[base0]=h0; olo[base0]=__float2bfloat16(v0-__bfloat162float(h0));
                ohi[base0+SEQL]=h1; olo[base0+SEQL]=__float2bfloat16(v1-__bfloat162float(h1));
            } else if(EPI==EPI_WO||EPI==EPI_W2){
                float2 o; o.x=v0; o.y=v1;
                *reinterpret_cast<float2*>(outf+(size_t)grow*FDIM+col)=o;
            } else if(EPI==EPI_W1){
                const size_t dst=(size_t)grow*MLPD+col;
                const float h0=__bfloat162float(__float2bfloat16(v0));
                const float h1=__bfloat162float(__float2bfloat16(v1));
                *reinterpret_cast<uint32_t*>(ohi+dst)=pk(v0,v1);
                *reinterpret_cast<uint32_t*>(olo+dst)=pk(v0-h0,v1-h1);
            }
        }
    }
}

// ---------------------------------------------------------------- flash attention
// 128 Q-rows per CTA, 4 warps x 32-row warp tiles. 64-key chunks, double-buffered.
// S = Q.K^T/8 (3-term hi/lo), online off-by-one softmax, P packed in regs, O += P.V (V hi/lo).
#define FL_QMAT (128*144)
#define FL_KMAT (64*144)
#define FL_KVBUF (4*FL_KMAT)
#define FL_SMEM (2*FL_QMAT + 2*FL_KVBUF)

__global__ __launch_bounds__(128)
void flash_kernel(const float* __restrict__ slim)
{
    extern __shared__ char sm[];
    const uint32_t sb=smem_u32(sm);
    const int tid=threadIdx.x, warp=tid>>5, lane=tid&31;
    const int gr=lane>>2, tc=lane&3;
    const int qt=blockIdx.x, bh=blockIdx.y, b=bh>>4, h=bh&15;

    const bf16* Qhg=g_q_hi + ((size_t)bh*SEQL + qt*128)*DHEAD;
    const bf16* Qlg=g_q_lo + ((size_t)bh*SEQL + qt*128)*DHEAD;
    const bf16* Khg=g_k_hi + (size_t)bh*SEQL*DHEAD;
    const bf16* Klg=g_k_lo + (size_t)bh*SEQL*DHEAD;
    const bf16* Vhg=g_vt_hi + (size_t)bh*DHEAD*SEQL;
    const bf16* Vlg=g_vt_lo + (size_t)bh*DHEAD*SEQL;

    // Q load: 128 rows x 8 chunks of 16B, hi+lo
#pragma unroll
    for(int it=0; it<8; ++it){
        const int u=tid+it*128, r=u>>3, ch=u&7;
        cp16(sb + r*144 + ch*16,           Qhg + (size_t)r*DHEAD + ch*8);
        cp16(sb + FL_QMAT + r*144 + ch*16, Qlg + (size_t)r*DHEAD + ch*8);
    }
    // KV chunk 0
    {
        const uint32_t bb=sb + 2*FL_QMAT;
#pragma unroll
        for(int it=0; it<4; ++it){
            const int u=tid+it*128, r=u>>3, ch=u&7;
            cp16(bb +             r*144 + ch*16, Khg + (size_t)r*DHEAD + ch*8);
            cp16(bb + FL_KMAT   + r*144 + ch*16, Klg + (size_t)r*DHEAD + ch*8);
            cp16(bb + 2*FL_KMAT + r*144 + ch*16, Vhg + (size_t)r*SEQL + ch*8);
            cp16(bb + 3*FL_KMAT + r*144 + ch*16, Vlg + (size_t)r*SEQL + ch*8);
        }
        CP_COMMIT();
    }

    float oacc[2][8][4];
#pragma unroll
    for(int i=0;i<2;i++)
#pragma unroll
        for(int j=0;j<8;j++){ oacc[i][j][0]=0.f;oacc[i][j][1]=0.f;oacc[i][j][2]=0.f;oacc[i][j][3]=0.f; }
    float mrun[4]={-1e30f,-1e30f,-1e30f,-1e30f}, srun[4]={0.f,0.f,0.f,0.f};

    for(int c=0;c<SEQL/64;c++){
        if(c+1<SEQL/64){
            const int j0=(c+1)*64;
            const uint32_t bb=sb + 2*FL_QMAT + ((c+1)&1)*FL_KVBUF;
#pragma unroll
            for(int it=0; it<4; ++it){
                const int u=tid+it*128, r=u>>3, ch=u&7;
                cp16(bb +             r*144 + ch*16, Khg + (size_t)(j0+r)*DHEAD + ch*8);
                cp16(bb + FL_KMAT   + r*144 + ch*16, Klg + (size_t)(j0+r)*DHEAD + ch*8);
                cp16(bb + 2*FL_KMAT + r*144 + ch*16, Vhg + (size_t)r*SEQL + j0 + ch*8);
                cp16(bb + 3*FL_KMAT + r*144 + ch*16, Vlg + (size_t)r*SEQL + j0 + ch*8);
            }
            CP_COMMIT();
            CP_WAIT(1);
        } else {
            CP_WAIT(0);
        }
        __syncthreads();

        const uint32_t bb=sb + 2*FL_QMAT + (c&1)*FL_KVBUF;
        const uint32_t KhB=bb, KlB=bb+FL_KMAT, VhB=bb+2*FL_KMAT, VlB=bb+3*FL_KMAT;

        // ---- S = Q.K^T (3-term) ----
        float sacc[2][8][4];
#pragma unroll
        for(int i=0;i<2;i++)
#pragma unroll
            for(int j=0;j<8;j++){ sacc[i][j][0]=0.f;sacc[i][j][1]=0.f;sacc[i][j][2]=0.f;sacc[i][j][3]=0.f; }
#pragma unroll
        for(int kd=0;kd<4;kd++){
            const uint32_t co=(kd*16+2*tc)*2;
            uint32_t qh[2][4], ql[2][4];
#pragma unroll
            for(int mt=0;mt<2;mt++){
                const int r=warp*32+mt*16+gr;
                qh[mt][0]=lds32(sb + r*144 + co);
                qh[mt][1]=lds32(sb + (r+8)*144 + co);
                qh[mt][2]=lds32(sb + r*144 + co + 16);
                qh[mt][3]=lds32(sb + (r+8)*144 + co + 16);
                ql[mt][0]=lds32(sb + FL_QMAT + r*144 + co);
                ql[mt][1]=lds32(sb + FL_QMAT + (r+8)*144 + co);
                ql[mt][2]=lds32(sb + FL_QMAT + r*144 + co + 16);
                ql[mt][3]=lds32(sb + FL_QMAT + (r+8)*144 + co + 16);
            }
#pragma unroll
            for(int nt=0;nt<8;nt++){
                const int n=nt*8+gr;
                const uint32_t kh0=lds32(KhB + n*144 + co), kh1=lds32(KhB + n*144 + co + 16);
                const uint32_t kl0=lds32(KlB + n*144 + co), kl1=lds32(KlB + n*144 + co + 16);
#pragma unroll
                for(int mt=0;mt<2;mt++){
                    mma16816(sacc[mt][nt], qh[mt][0],qh[mt][1],qh[mt][2],qh[mt][3], kh0,kh1);
                    mma16816(sacc[mt][nt], qh[mt][0],qh[mt][1],qh[mt][2],qh[mt][3], kl0,kl1);
                    mma16816(sacc[mt][nt], ql[mt][0],ql[mt][1],ql[mt][2],ql[mt][3], kh0,kh1);
                }
            }
        }
        // scale 1/sqrt(64)
#pragma unroll
        for(int mt=0;mt<2;mt++)
#pragma unroll
            for(int nt=0;nt<8;nt++)
#pragma unroll
                for(int i=0;i<4;i++) sacc[mt][nt][i]*=0.125f;

        // ---- online softmax per row ----
#pragma unroll
        for(int mt=0;mt<2;mt++)
#pragma unroll
        for(int hf=0;hf<2;hf++){
            const int ri=mt*2+hf;
            float rmax=-1e30f;
#pragma unroll
            for(int nt=0;nt<8;nt++){ rmax=fmaxf(rmax,fmaxf(sacc[mt][nt][2*hf],sacc[mt][nt][2*hf+1])); }
            rmax=fmaxf(rmax,__shfl_xor_sync(~0u,rmax,1));
            rmax=fmaxf(rmax,__shfl_xor_sync(~0u,rmax,2));
            const float mnew=fmaxf(mrun[ri],rmax);
            const float corr=__expf(mrun[ri]-mnew);
            float sum=0.f;
#pragma unroll
            for(int nt=0;nt<8;nt++){
                const float e0=__expf(sacc[mt][nt][2*hf]-mnew);
                const float e1=__expf(sacc[mt][nt][2*hf+1]-mnew);
                sacc[mt][nt][2*hf]=e0; sacc[mt][nt][2*hf+1]=e1;
                sum+=e0+e1;
            }
            sum+=__shfl_xor_sync(~0u,sum,1);
            sum+=__shfl_xor_sync(~0u,sum,2);
            srun[ri]=srun[ri]*corr+sum;
            mrun[ri]=mnew;
#pragma unroll
            for(int nd=0;nd<8;nd++){ oacc[mt][nd][2*hf]*=corr; oacc[mt][nd][2*hf+1]*=corr; }
        }

        // ---- O += P.V (P from regs, V hi/lo) ----
#pragma unroll
        for(int kk=0;kk<4;kk++){
            uint32_t a[2][4];
#pragma unroll
            for(int mt=0;mt<2;mt++){
                a[mt][0]=pk(sacc[mt][2*kk][0],  sacc[mt][2*kk][1]);
                a[mt][1]=pk(sacc[mt][2*kk][2],  sacc[mt][2*kk][3]);
                a[mt][2]=pk(sacc[mt][2*kk+1][0],sacc[mt][2*kk+1][1]);
                a[mt][3]=pk(sacc[mt][2*kk+1][2],sacc[mt][2*kk+1][3]);
            }
            const uint32_t co=(kk*16+2*tc)*2;
#pragma unroll
            for(int nd=0;nd<8;nd++){
                const int n=nd*8+gr;
                const uint32_t vh0=lds32(VhB + n*144 + co), vh1=lds32(VhB + n*144 + co + 16);
                const uint32_t vl0=lds32(VlB + n*144 + co), vl1=lds32(VlB + n*144 + co + 16);
#pragma unroll
                for(int mt=0;mt<2;mt++){
                    mma16816(oacc[mt][nd], a[mt][0],a[mt][1],a[mt][2],a[mt][3], vh0,vh1);
                    mma16816(oacc[mt][nd], a[mt][0],a[mt][1],a[mt][2],a[mt][3], vl0,vl1);
                }
            }
        }
        __syncthreads();
    }

    // ---- final scale + store (off-by-one denom, slim) ----
    const float sl=__ldg(slim+h);
    float sc[4];
#pragma unroll
    for(int ri=0;ri<4;ri++) sc[ri]=sl/(srun[ri]+__expf(-mrun[ri]));
#pragma unroll
    for(int mt=0;mt<2;mt++)
#pragma unroll
    for(int hf=0;hf<2;hf++){
        const int ri=mt*2+hf;
        const int grow=qt*128+warp*32+mt*16+gr+8*hf;
        const size_t rowoff=((size_t)(b*SEQL+grow))*FDIM + h*DHEAD;
#pragma unroll
        for(int nd=0;nd<8;nd++){
            const int col=nd*8+2*tc;
            const float v0=oacc[mt][nd][2*hf]*sc[ri], v1=oacc[mt][nd][2*hf+1]*sc[ri];
            const float h0=__bfloat162float(__float2bfloat16(v0));
            const float h1=__bfloat162float(__float2bfloat16(v1));
            *reinterpret_cast<uint32_t*>(g_at_hi+rowoff+col)=pk(v0,v1);
            *reinterpret_cast<uint32_t*>(g_at_lo+rowoff+col)=pk(v0-h0,v1-h1);
        }
    }
}

__global__ __launch_bounds__(256)
void ln_kernel(const float* __restrict__ x, const float* __restrict__ g,
               const float* __restrict__ b, bf16* __restrict__ yhi, bf16* __restrict__ ylo)
{
    __shared__ float red[16];
    const int row=blockIdx.x, tid=threadIdx.x;
    const float4 v=reinterpret_cast<const float4*>(x+(size_t)row*FDIM)[tid];
    float s=v.x+v.y+v.z+v.w, s2=v.x*v.x+v.y*v.y+v.z*v.z+v.w*v.w;
#pragma unroll
    for(int o=16;o>0;o>>=1){ s+=__shfl_xor_sync(~0u,s,o); s2+=__shfl_xor_sync(~0u,s2,o); }
    const int warp=tid>>5, lane=tid&31;
    if(lane==0){ red[warp]=s; red[8+warp]=s2; }
    __syncthreads();
    float ts=0.f, ts2=0.f;
#pragma unroll
    for(int i=0;i<8;i++){ ts+=red[i]; ts2+=red[8+i]; }
    const float mu=ts*(1.f/FDIM), var=ts2*(1.f/FDIM)-mu*mu, inv=rsqrtf(var+LN_EPS);
    const float4 gg=reinterpret_cast<const float4*>(g)[tid];
    const float4 bb=reinterpret_cast<const float4*>(b)[tid];
    const float o0=(v.x-mu)*inv*gg.x+bb.x, o1=(v.y-mu)*inv*gg.y+bb.y;
    const float o2=(v.z-mu)*inv*gg.z+bb.z, o3=(v.w-mu)*inv*gg.w+bb.w;
    const float h0=__bfloat162float(__float2bfloat16(o0)), h1=__bfloat162float(__float2bfloat16(o1));
    const float h2=__bfloat162float(__float2bfloat16(o2)), h3=__bfloat162float(__float2bfloat16(o3));
    uint2 H,L;
    H.x=pk(o0,o1); H.y=pk(o2,o3);
    L.x=pk(o0-h0,o1-h1); L.y=pk(o2-h2,o3-h3);
    const size_t dst=(size_t)row*FDIM+tid*4;
    *reinterpret_cast<uint2*>(yhi+dst)=H;
    *reinterpret_cast<uint2*>(ylo+dst)=L;
}

__global__ __launch_bounds__(256)
void wconv_kernel(const float* __restrict__ W, bf16* __restrict__ hi, bf16* __restrict__ lo, int K, int N)
{
    __shared__ float s[32][33];
    const int n0=blockIdx.x*32, k0=blockIdx.y*32;
    const int tx=threadIdx.x, ty=threadIdx.y;
#pragma unroll
    for(int j=0;j<4;j++) s[ty+8*j][tx]=W[(size_t)(k0+ty+8*j)*N+n0+tx];
    __syncthreads();
#pragma unroll
    for(int j=0;j<4;j++){
        const float v=s[tx][ty+8*j];
        const bf16 h=__float2bfloat16(v);
        const size_t dst=(size_t)(n0+ty+8*j)*K+k0+tx;
        hi[dst]=h; lo[dst]=__float2bfloat16(v-__bfloat162float(h));
    }
}

static void* sym_addr(const void* s){ void* p=nullptr; cudaGetSymbolAddress(&p,s); return p; }

extern "C" void kernel_launch(void* const* d_in, const int* in_sizes, int n_in,
                              void* d_out, int out_size)
{
    const float* x=(const float*)d_in[0];
    const float* ln1_g=(const float*)d_in[1]; const float* ln1_b=(const float*)d_in[2];
    const float* Wq=(const float*)d_in[3];  const float* bq=(const float*)d_in[4];
    const float* Wk=(const float*)d_in[5];  const float* bk=(const float*)d_in[6];
    const float* Wv=(const float*)d_in[7];  const float* bv=(const float*)d_in[8];
    const float* Wo=(const float*)d_in[9];  const float* bo=(const float*)d_in[10];
    const float* slim=(const float*)d_in[11];
    const float* ln2_g=(const float*)d_in[12]; const float* ln2_b=(const float*)d_in[13];
    const float* W1=(const float*)d_in[14]; const float* b1=(const float*)d_in[15];
    const float* W2=(const float*)d_in[16]; const float* b2=(const float*)d_in[17];
    float* out=(float*)d_out;

    bf16 *h_hi=(bf16*)sym_addr(g_h_hi), *h_lo=(bf16*)sym_addr(g_h_lo);
    bf16 *q_hi=(bf16*)sym_addr(g_q_hi), *q_lo=(bf16*)sym_addr(g_q_lo);
    bf16 *k_hi=(bf16*)sym_addr(g_k_hi), *k_lo=(bf16*)sym_addr(g_k_lo);
    bf16 *vt_hi=(bf16*)sym_addr(g_vt_hi), *vt_lo=(bf16*)sym_addr(g_vt_lo);
    bf16 *at_hi=(bf16*)sym_addr(g_at_hi), *at_lo=(bf16*)sym_addr(g_at_lo);
    bf16 *m1_hi=(bf16*)sym_addr(g_m1_hi), *m1_lo=(bf16*)sym_addr(g_m1_lo);
    float* out1=(float*)sym_addr(g_out1);
    bf16 *wqh=(bf16*)sym_addr(g_wq_hi), *wql=(bf16*)sym_addr(g_wq_lo);
    bf16 *wkh=(bf16*)sym_addr(g_wk_hi), *wkl=(bf16*)sym_addr(g_wk_lo);
    bf16 *wvh=(bf16*)sym_addr(g_wv_hi), *wvl=(bf16*)sym_addr(g_wv_lo);
    bf16 *woh=(bf16*)sym_addr(g_wo_hi), *wol=(bf16*)sym_addr(g_wo_lo);
    bf16 *w1h=(bf16*)sym_addr(g_w1_hi), *w1l=(bf16*)sym_addr(g_w1_lo);
    bf16 *w2h=(bf16*)sym_addr(g_w2_hi), *w2l=(bf16*)sym_addr(g_w2_lo);

    constexpr int SM3=81920;
    cudaFuncSetAttribute(gemm_mma<128,3,EPI_QK>, cudaFuncAttributeMaxDynamicSharedMemorySize, SM3);
    cudaFuncSetAttribute(gemm_mma<128,3,EPI_V >, cudaFuncAttributeMaxDynamicSharedMemorySize, SM3);
    cudaFuncSetAttribute(gemm_mma<128,3,EPI_WO>, cudaFuncAttributeMaxDynamicSharedMemorySize, SM3);
    cudaFuncSetAttribute(gemm_mma<128,3,EPI_W1>, cudaFuncAttributeMaxDynamicSharedMemorySize, SM3);
    cudaFuncSetAttribute(gemm_mma<128,3,EPI_W2>, cudaFuncAttributeMaxDynamicSharedMemorySize, SM3);
    cudaFuncSetAttribute(flash_kernel, cudaFuncAttributeMaxDynamicSharedMemorySize, FL_SMEM);

    const dim3 wb(32,8);
    wconv_kernel<<<dim3(FDIM/32,FDIM/32),wb>>>(Wq,wqh,wql,FDIM,FDIM);
    wconv_kernel<<<dim3(FDIM/32,FDIM/32),wb>>>(Wk,wkh,wkl,FDIM,FDIM);
    wconv_kernel<<<dim3(FDIM/32,FDIM/32),wb>>>(Wv,wvh,wvl,FDIM,FDIM);
    wconv_kernel<<<dim3(FDIM/32,FDIM/32),wb>>>(Wo,woh,wol,FDIM,FDIM);
    wconv_kernel<<<dim3(MLPD/32,FDIM/32),wb>>>(W1,w1h,w1l,FDIM,MLPD);
    wconv_kernel<<<dim3(FDIM/32,MLPD/32),wb>>>(W2,w2h,w2l,MLPD,FDIM);

    ln_kernel<<<TT,256>>>(x,ln1_g,ln1_b,h_hi,h_lo);

    gemm_mma<128,3,EPI_QK><<<dim3(8,32,1),256,SM3>>>(h_hi,h_lo,wqh,wql,FDIM,0,0,bq,nullptr,nullptr,q_hi,q_lo);
    gemm_mma<128,3,EPI_QK><<<dim3(8,32,1),256,SM3>>>(h_hi,h_lo,wkh,wkl,FDIM,0,0,bk,nullptr,nullptr,k_hi,k_lo);
    gemm_mma<128,3,EPI_V ><<<dim3(8,32,1),256,SM3>>>(h_hi,h_lo,wvh,wvl,FDIM,0,0,bv,nullptr,nullptr,vt_hi,vt_lo);

    // fused flash attention (off-by-one softmax, slim folded)
    flash_kernel<<<dim3(SEQL/128,32),128,FL_SMEM>>>(slim);

    gemm_mma<128,3,EPI_WO><<<dim3(8,32,1),256,SM3>>>(at_hi,at_lo,woh,wol,FDIM,0,0,bo,x,out1,nullptr,nullptr);

    ln_kernel<<<TT,256>>>(out1,ln2_g,ln2_b,h_hi,h_lo);

    gemm_mma<128,3,EPI_W1><<<dim3(32,32,1),256,SM3>>>(h_hi,h_lo,w1h,w1l,FDIM,0,0,b1,nullptr,nullptr,m1_hi,m1_lo);
    gemm_mma<128,3,EPI_W2><<<dim3(8,32,1),256,SM3>>>(m1_hi,m1_lo,w2h,w2l,MLPD,0,0,b2,out1,out,nullptr,nullptr);
}